// round 14
// baseline (speedup 1.0000x reference)
#include <cuda_runtime.h>
#include <cstdint>

#define PP 64
#define TT 8192
#define KK 8
#define NN 8189            // N = T - HIST - 1
#define NPAD 8192          // padded event count (16B-aligned rows)
#define NPAST 64
#define NSTATE 4096        // NPAST * NPAST
#define HIST_U32 8192      // 32768 u8 counts packed into u32 (32 KB)
#define NPAIR (PP*(PP-1))  // 4032

// scratch (no cudaMalloc allowed)
__device__ float    g_cm[PP][TT];    // column-major copy of input
__device__ uint16_t g_a[PP][NPAD];   // (yp*128 + (yf>>2)) | ((yf&3)<<14)
__device__ uint16_t g_b[PP][NPAD];   // xp*2
__device__ float    g_hy[PP];        // H(y | y_past) per target column

// ---------------------------------------------------------------------------
// K0: tiled transpose, 256 blocks x 1024 threads (R12/R13 exact).
// ---------------------------------------------------------------------------
__global__ __launch_bounds__(1024) void transpose_kernel(const float* __restrict__ ts)
{
    __shared__ float tile[32][65];
    const int r0   = blockIdx.x * 32;
    const int base = blockIdx.x * 2048;
    const int tid  = threadIdx.x;

    #pragma unroll
    for (int k = 0; k < 2; k++) {
        int i = tid + k * 1024;            // 0..2047
        tile[i >> 6][i & 63] = ts[base + i];
    }
    __syncthreads();
    #pragma unroll
    for (int k = 0; k < 2; k++) {
        int i = tid + k * 1024;
        int c = i >> 5, r = i & 31;
        g_cm[c][r0 + r] = tile[r][c];      // coalesced, conflict-free
    }
}

// ---------------------------------------------------------------------------
// K1: per-column prep, 64 blocks x 1024 threads (R13 exact, incl. PDL).
// ---------------------------------------------------------------------------
__global__ __launch_bounds__(1024) void prep_kernel(float* __restrict__ out)
{
    __shared__ float    s_col[TT];          // 32 KB
    __shared__ uint8_t  s_dig[TT];          // 8 KB
    __shared__ float    s_mn[32], s_mx[32];
    __shared__ float    s_par[2];           // xmin, den
    __shared__ int      s_flat;
    __shared__ unsigned s_cy[NPAST * KK];
    __shared__ float    s_term[NPAST];

    const int p    = blockIdx.x;
    const int tid  = threadIdx.x;
    const int lane = tid & 31;
    const int wid  = tid >> 5;

    // independent prefix: zero cy + diagonal output
    for (int i = tid; i < NPAST * KK; i += 1024) s_cy[i] = 0u;
    if (tid == 0) out[p * 65] = 0.0f;       // diagonal output element

    // wait for transpose grid before touching g_cm
    cudaGridDependencySynchronize();

    float mn =  3.402823466e38f;
    float mx = -3.402823466e38f;
    const float4* c4 = (const float4*)&g_cm[p][0];
    float4*       s4 = (float4*)s_col;
    #pragma unroll
    for (int i = tid; i < TT / 4; i += 1024) {
        float4 v = c4[i];
        s4[i] = v;
        mn = fminf(mn, fminf(fminf(v.x, v.y), fminf(v.z, v.w)));
        mx = fmaxf(mx, fmaxf(fmaxf(v.x, v.y), fmaxf(v.z, v.w)));
    }
    #pragma unroll
    for (int o = 16; o; o >>= 1) {
        mn = fminf(mn, __shfl_xor_sync(0xffffffffu, mn, o));
        mx = fmaxf(mx, __shfl_xor_sync(0xffffffffu, mx, o));
    }
    if (lane == 0) { s_mn[wid] = mn; s_mx[wid] = mx; }
    __syncthreads();
    if (tid == 0) {
        float m = s_mn[0], M = s_mx[0];
        for (int i = 1; i < 32; i++) { m = fminf(m, s_mn[i]); M = fmaxf(M, s_mx[i]); }
        float rng = __fsub_rn(M, m);
        s_par[0] = m;
        s_par[1] = __fadd_rn(rng, 1e-8f);
        s_flat   = (rng < 1e-8f);
    }
    __syncthreads();

    const float xmin = s_par[0];
    const float den  = s_par[1];
    const int   flat = s_flat;

    for (int t = tid; t < TT; t += 1024) {
        float norm = __fdiv_rn(__fsub_rn(s_col[t], xmin), den);
        int b = (int)__fmul_rn(norm, 7.0f);   // trunc toward zero, norm >= 0
        b = min(max(b, 0), KK - 1);
        s_dig[t] = flat ? (uint8_t)0 : (uint8_t)b;
    }
    __syncthreads();

    for (int i = tid; i < NPAD; i += 1024) {
        if (i < NN) {
            unsigned d1 = s_dig[i + 1], d2 = s_dig[i + 2], d3 = s_dig[i + 3];
            unsigned yp = d2 + 8u * d1;
            g_a[p][i] = (uint16_t)((yp * 128u + (d3 >> 2)) | ((d3 & 3u) << 14));
            g_b[p][i] = (uint16_t)(yp * 2u);
            atomicAdd(&s_cy[yp * KK + d3], 1u);
        } else {
            g_a[p][i] = 0;
            g_b[p][i] = 0;
        }
    }
    __syncthreads();

    if (tid < NPAST) {
        unsigned tot = 0;
        float acc = 0.0f;
        #pragma unroll
        for (int y = 0; y < KK; y++) {
            unsigned c = s_cy[tid * KK + y];
            tot += c;
            if (c >= 2) acc -= (float)c * __log2f((float)c);
        }
        if (tot >= 2) acc += (float)tot * __log2f((float)tot);
        else          acc  = 0.0f;    // tot in {0,1} contributes exactly 0
        s_term[tid] = acc;
    }
    __syncthreads();
    if (tid == 0) {
        float h = 0.0f;
        for (int i = 0; i < NPAST; i++) h += s_term[i];
        g_hy[p] = h / (float)NN;
    }
}

// ---------------------------------------------------------------------------
// K2: pair kernel — R3 body, EXCEPT the sweep walks states via conflict-free
// LDS.128 (uint4 = 2 consecutive states), so warps own 64-state contiguous
// chunks and the empty-skip branch takes coherently.
// ---------------------------------------------------------------------------
__device__ __forceinline__ void bump2u8(unsigned* h, unsigned sum)
{
    // low half: word = sum & 0x3fff, shift = ((sum>>14)&3)*8 = (sum>>11)&0x18
    atomicAdd(&h[sum & 0x3fffu],         1u << ((sum >> 11) & 0x18u));
    atomicAdd(&h[(sum >> 16) & 0x3fffu], 1u << ((sum >> 27) & 0x18u));
}

// One state's contribution (EXACT R3 per-state body).
__device__ __forceinline__ void ent_state(float& acc, unsigned lo, unsigned hi)
{
    if (lo | hi) {
        unsigned ps  = lo + hi;                       // byte-wise, carry-free
        unsigned tot = __dp4a(ps, 0x01010101u, 0u);   // sum of all 8 bytes
        if (tot >= 2) {
            float a2 = (float)tot * __log2f((float)tot);
            #pragma unroll
            for (int k = 0; k < 4; k++) {
                unsigned c0 = (lo >> (k * 8)) & 0xffu;
                if (c0 >= 2) a2 -= (float)c0 * __log2f((float)c0);
                unsigned c1 = (hi >> (k * 8)) & 0xffu;
                if (c1 >= 2) a2 -= (float)c1 * __log2f((float)c1);
            }
            acc += a2;
        }
    }
}

__global__ __launch_bounds__(512) void pair_kernel(float* __restrict__ out)
{
    __shared__ unsigned s_hist[HIST_U32];   // 32 KB

    const int job = blockIdx.x;             // 0..4031
    const int s   = job / 63;
    const int r   = job - s * 63;
    const int t   = r + (r >= s ? 1 : 0);   // skip diagonal
    const int tid = threadIdx.x;

    // independent prefix: zero histogram (overlaps prep's tail under PDL)
    uint4* h4 = (uint4*)s_hist;
    #pragma unroll
    for (int i = tid; i < HIST_U32 / 4; i += 512)
        h4[i] = make_uint4(0u, 0u, 0u, 0u);

    // wait for prep grid before reading g_a / g_b / g_hy
    cudaGridDependencySynchronize();
    __syncthreads();

    // build joint histogram: 2 uint4-pairs per thread (16 events)
    const uint4* __restrict__ A = (const uint4*)&g_a[t][0];
    const uint4* __restrict__ B = (const uint4*)&g_b[s][0];
    #pragma unroll
    for (int c = 0; c < 2; c++) {
        int u = tid + c * 512;               // uint4 index, 0..1023
        uint4 va = A[u];
        uint4 vb = B[u];
        if (u != 1023) {                     // 8 valid events
            bump2u8(s_hist, va.x + vb.x);
            bump2u8(s_hist, va.y + vb.y);
            bump2u8(s_hist, va.z + vb.z);
            bump2u8(s_hist, va.w + vb.w);
        } else {                             // events 8184..8188 valid (5)
            bump2u8(s_hist, va.x + vb.x);
            bump2u8(s_hist, va.y + vb.y);
            unsigned sum = va.z + vb.z;      // event 8188 = low half only
            atomicAdd(&s_hist[sum & 0x3fffu], 1u << ((sum >> 11) & 0x18u));
        }
    }
    __syncthreads();

    // entropy sweep: uint4 = 2 consecutive states; lane stride 16B ->
    // conflict-free LDS.128; warp covers 64 contiguous states per k.
    float acc = 0.0f;
    #pragma unroll
    for (int k = 0; k < 4; k++) {
        uint4 v = h4[tid + k * 512];
        ent_state(acc, v.x, v.y);
        ent_state(acc, v.z, v.w);
    }
    __syncthreads();   // everyone done reading hist before reuse as scratch

    // block reduce (16 warps)
    #pragma unroll
    for (int o = 16; o; o >>= 1)
        acc += __shfl_xor_sync(0xffffffffu, acc, o);
    float* sr = (float*)s_hist;
    if ((tid & 31) == 0) sr[tid >> 5] = acc;
    __syncthreads();
    if (tid == 0) {
        float tt = 0.0f;
        #pragma unroll
        for (int w = 0; w < 16; w++) tt += sr[w];
        float h_ypxp = tt / (float)NN;
        out[s * 64 + t] = fmaxf(0.0f, g_hy[t] - h_ypxp);
    }
}

// ---------------------------------------------------------------------------
extern "C" void kernel_launch(void* const* d_in, const int* in_sizes, int n_in,
                              void* d_out, int out_size)
{
    const float* ts = (const float*)d_in[0];
    float* out = (float*)d_out;

    transpose_kernel<<<TT / 32, 1024>>>(ts);

    cudaLaunchAttribute attr[1];
    attr[0].id = cudaLaunchAttributeProgrammaticStreamSerialization;
    attr[0].val.programmaticStreamSerializationAllowed = 1;

    {
        cudaLaunchConfig_t cfg = {};
        cfg.gridDim  = dim3(PP, 1, 1);
        cfg.blockDim = dim3(1024, 1, 1);
        cfg.attrs    = attr;
        cfg.numAttrs = 1;
        cudaLaunchKernelEx(&cfg, prep_kernel, out);
    }
    {
        cudaLaunchConfig_t cfg = {};
        cfg.gridDim  = dim3(NPAIR, 1, 1);
        cfg.blockDim = dim3(512, 1, 1);
        cfg.attrs    = attr;
        cfg.numAttrs = 1;
        cudaLaunchKernelEx(&cfg, pair_kernel, out);
    }
}

// round 15
// speedup vs baseline: 1.0439x; 1.0439x over previous
#include <cuda_runtime.h>
#include <cstdint>

#define PP 64
#define TT 8192
#define KK 8
#define NN 8189            // N = T - HIST - 1
#define NPAD 8192          // padded event count (16B-aligned rows)
#define NPAST 64
#define NSTATE 4096        // NPAST * NPAST
#define HIST_U32 8192      // 32768 u8 counts packed into u32 (32 KB)
#define NPAIR (PP*(PP-1))  // 4032

// scratch (no cudaMalloc allowed)
__device__ float    g_cm[PP][TT];    // column-major copy of input
__device__ uint16_t g_a[PP][NPAD];   // (yp*128 + (yf>>2)) | ((yf&3)<<14)
__device__ uint16_t g_b[PP][NPAD];   // xp*2
__device__ float    g_hy[PP];        // H(y | y_past) per target column

// ---------------------------------------------------------------------------
// K0: tiled transpose, 256 blocks x 1024 threads (R13 exact).
// ---------------------------------------------------------------------------
__global__ __launch_bounds__(1024) void transpose_kernel(const float* __restrict__ ts)
{
    __shared__ float tile[32][65];
    const int r0   = blockIdx.x * 32;
    const int base = blockIdx.x * 2048;
    const int tid  = threadIdx.x;

    #pragma unroll
    for (int k = 0; k < 2; k++) {
        int i = tid + k * 1024;            // 0..2047
        tile[i >> 6][i & 63] = ts[base + i];
    }
    __syncthreads();
    #pragma unroll
    for (int k = 0; k < 2; k++) {
        int i = tid + k * 1024;
        int c = i >> 5, r = i & 31;
        g_cm[c][r0 + r] = tile[r][c];      // coalesced, conflict-free
    }
}

// ---------------------------------------------------------------------------
// K1: per-column prep, 64 blocks x 1024 threads (R13 exact, incl. PDL).
// ---------------------------------------------------------------------------
__global__ __launch_bounds__(1024) void prep_kernel(float* __restrict__ out)
{
    __shared__ float    s_col[TT];          // 32 KB
    __shared__ uint8_t  s_dig[TT];          // 8 KB
    __shared__ float    s_mn[32], s_mx[32];
    __shared__ float    s_par[2];           // xmin, den
    __shared__ int      s_flat;
    __shared__ unsigned s_cy[NPAST * KK];
    __shared__ float    s_term[NPAST];

    const int p    = blockIdx.x;
    const int tid  = threadIdx.x;
    const int lane = tid & 31;
    const int wid  = tid >> 5;

    // independent prefix: zero cy + diagonal output
    for (int i = tid; i < NPAST * KK; i += 1024) s_cy[i] = 0u;
    if (tid == 0) out[p * 65] = 0.0f;       // diagonal output element

    // wait for transpose grid before touching g_cm
    cudaGridDependencySynchronize();

    float mn =  3.402823466e38f;
    float mx = -3.402823466e38f;
    const float4* c4 = (const float4*)&g_cm[p][0];
    float4*       s4 = (float4*)s_col;
    #pragma unroll
    for (int i = tid; i < TT / 4; i += 1024) {
        float4 v = c4[i];
        s4[i] = v;
        mn = fminf(mn, fminf(fminf(v.x, v.y), fminf(v.z, v.w)));
        mx = fmaxf(mx, fmaxf(fmaxf(v.x, v.y), fmaxf(v.z, v.w)));
    }
    #pragma unroll
    for (int o = 16; o; o >>= 1) {
        mn = fminf(mn, __shfl_xor_sync(0xffffffffu, mn, o));
        mx = fmaxf(mx, __shfl_xor_sync(0xffffffffu, mx, o));
    }
    if (lane == 0) { s_mn[wid] = mn; s_mx[wid] = mx; }
    __syncthreads();
    if (tid == 0) {
        float m = s_mn[0], M = s_mx[0];
        for (int i = 1; i < 32; i++) { m = fminf(m, s_mn[i]); M = fmaxf(M, s_mx[i]); }
        float rng = __fsub_rn(M, m);
        s_par[0] = m;
        s_par[1] = __fadd_rn(rng, 1e-8f);
        s_flat   = (rng < 1e-8f);
    }
    __syncthreads();

    const float xmin = s_par[0];
    const float den  = s_par[1];
    const int   flat = s_flat;

    for (int t = tid; t < TT; t += 1024) {
        float norm = __fdiv_rn(__fsub_rn(s_col[t], xmin), den);
        int b = (int)__fmul_rn(norm, 7.0f);   // trunc toward zero, norm >= 0
        b = min(max(b, 0), KK - 1);
        s_dig[t] = flat ? (uint8_t)0 : (uint8_t)b;
    }
    __syncthreads();

    for (int i = tid; i < NPAD; i += 1024) {
        if (i < NN) {
            unsigned d1 = s_dig[i + 1], d2 = s_dig[i + 2], d3 = s_dig[i + 3];
            unsigned yp = d2 + 8u * d1;
            g_a[p][i] = (uint16_t)((yp * 128u + (d3 >> 2)) | ((d3 & 3u) << 14));
            g_b[p][i] = (uint16_t)(yp * 2u);
            atomicAdd(&s_cy[yp * KK + d3], 1u);
        } else {
            g_a[p][i] = 0;
            g_b[p][i] = 0;
        }
    }
    __syncthreads();

    if (tid < NPAST) {
        unsigned tot = 0;
        float acc = 0.0f;
        #pragma unroll
        for (int y = 0; y < KK; y++) {
            unsigned c = s_cy[tid * KK + y];
            tot += c;
            if (c >= 2) acc -= (float)c * __log2f((float)c);
        }
        if (tot >= 2) acc += (float)tot * __log2f((float)tot);
        else          acc  = 0.0f;    // tot in {0,1} contributes exactly 0
        s_term[tid] = acc;
    }
    __syncthreads();
    if (tid == 0) {
        float h = 0.0f;
        for (int i = 0; i < NPAST; i++) h += s_term[i];
        g_hy[p] = h / (float)NN;
    }
}

// ---------------------------------------------------------------------------
// K2: pair kernel — R13 exact body EXCEPT: the event loop is now uniform
// (no tail branch; the 3 padded events land in bin 0 and are removed by a
// single atomicAdd(-3) from thread 0 before the barrier).
// ---------------------------------------------------------------------------
__device__ __forceinline__ void bump2u8(unsigned* h, unsigned sum)
{
    // low half: word = sum & 0x3fff, shift = ((sum>>14)&3)*8 = (sum>>11)&0x18
    atomicAdd(&h[sum & 0x3fffu],         1u << ((sum >> 11) & 0x18u));
    atomicAdd(&h[(sum >> 16) & 0x3fffu], 1u << ((sum >> 27) & 0x18u));
}

__global__ __launch_bounds__(512) void pair_kernel(float* __restrict__ out)
{
    __shared__ unsigned s_hist[HIST_U32];   // 32 KB

    const int job = blockIdx.x;             // 0..4031
    const int s   = job / 63;
    const int r   = job - s * 63;
    const int t   = r + (r >= s ? 1 : 0);   // skip diagonal
    const int tid = threadIdx.x;

    // independent prefix: zero histogram (overlaps prep's tail under PDL)
    uint4* h4 = (uint4*)s_hist;
    #pragma unroll
    for (int i = tid; i < HIST_U32 / 4; i += 512)
        h4[i] = make_uint4(0u, 0u, 0u, 0u);

    // wait for prep grid before reading g_a / g_b / g_hy
    cudaGridDependencySynchronize();
    __syncthreads();

    // build joint histogram: uniform loop, 16 events per thread.
    // The 3 padded events (g_a=g_b=0) hit bin 0; corrected below.
    const uint4* __restrict__ A = (const uint4*)&g_a[t][0];
    const uint4* __restrict__ B = (const uint4*)&g_b[s][0];
    #pragma unroll
    for (int c = 0; c < 2; c++) {
        int u = tid + c * 512;               // uint4 index, 0..1023
        uint4 va = A[u];
        uint4 vb = B[u];
        bump2u8(s_hist, va.x + vb.x);
        bump2u8(s_hist, va.y + vb.y);
        bump2u8(s_hist, va.z + vb.z);
        bump2u8(s_hist, va.w + vb.w);
    }
    if (tid == 0)
        atomicAdd(&s_hist[0], (unsigned)-3);  // remove the 3 padding counts
    __syncthreads();

    // entropy sweep: state st owns 8 u8 counts = one uint2 (R3/R13 exact)
    float acc = 0.0f;
    const uint2* h2 = (const uint2*)s_hist;
    #pragma unroll
    for (int st = tid; st < NSTATE; st += 512) {
        uint2 v = h2[st];
        if (v.x | v.y) {
            unsigned ps  = v.x + v.y;                     // byte-wise, carry-free
            unsigned tot = __dp4a(ps, 0x01010101u, 0u);   // sum of all 8 bytes
            if (tot >= 2) {
                float a2 = (float)tot * __log2f((float)tot);
                #pragma unroll
                for (int k = 0; k < 4; k++) {
                    unsigned c0 = (v.x >> (k * 8)) & 0xffu;
                    if (c0 >= 2) a2 -= (float)c0 * __log2f((float)c0);
                    unsigned c1 = (v.y >> (k * 8)) & 0xffu;
                    if (c1 >= 2) a2 -= (float)c1 * __log2f((float)c1);
                }
                acc += a2;
            }
        }
    }
    __syncthreads();   // everyone done reading hist before reuse as scratch

    // block reduce (16 warps)
    #pragma unroll
    for (int o = 16; o; o >>= 1)
        acc += __shfl_xor_sync(0xffffffffu, acc, o);
    float* sr = (float*)s_hist;
    if ((tid & 31) == 0) sr[tid >> 5] = acc;
    __syncthreads();
    if (tid == 0) {
        float tt = 0.0f;
        #pragma unroll
        for (int w = 0; w < 16; w++) tt += sr[w];
        float h_ypxp = tt / (float)NN;
        out[s * 64 + t] = fmaxf(0.0f, g_hy[t] - h_ypxp);
    }
}

// ---------------------------------------------------------------------------
extern "C" void kernel_launch(void* const* d_in, const int* in_sizes, int n_in,
                              void* d_out, int out_size)
{
    const float* ts = (const float*)d_in[0];
    float* out = (float*)d_out;

    transpose_kernel<<<TT / 32, 1024>>>(ts);

    cudaLaunchAttribute attr[1];
    attr[0].id = cudaLaunchAttributeProgrammaticStreamSerialization;
    attr[0].val.programmaticStreamSerializationAllowed = 1;

    {
        cudaLaunchConfig_t cfg = {};
        cfg.gridDim  = dim3(PP, 1, 1);
        cfg.blockDim = dim3(1024, 1, 1);
        cfg.attrs    = attr;
        cfg.numAttrs = 1;
        cudaLaunchKernelEx(&cfg, prep_kernel, out);
    }
    {
        cudaLaunchConfig_t cfg = {};
        cfg.gridDim  = dim3(NPAIR, 1, 1);
        cfg.blockDim = dim3(512, 1, 1);
        cfg.attrs    = attr;
        cfg.numAttrs = 1;
        cudaLaunchKernelEx(&cfg, pair_kernel, out);
    }
}